// round 2
// baseline (speedup 1.0000x reference)
#include <cuda_runtime.h>
#include <math.h>

#define NN 100000
#define EE 1000000
#define RR 40
#define DD 64

static constexpr float PHASE_SCALE = (float)(3.1415926235897933 / ((12.0 + 2.0) / 64.0));

// ---- scratch (device globals: no runtime allocation allowed) ----
__device__ int   g_cnt[NN];
__device__ int   g_cursor[NN];
__device__ int   g_rowptr[NN + 1];
__device__ int   g_src_p[EE];
__device__ int   g_dst_p[EE];
__device__ int   g_typ_p[EE];
__device__ float g_att[EE];
__device__ float g_side[(size_t)NN * 128];
__device__ float g_ego1[(size_t)NN * 64];
__device__ float g_ego2[(size_t)NN * 32];
__device__ float g_ego3[(size_t)NN * 16];
__device__ float g_cr[RR * DD];
__device__ float g_sr[RR * DD];

__device__ __forceinline__ float fsqrt_approx(float x) {
    float y; asm("sqrt.approx.f32 %0, %1;" : "=f"(y) : "f"(x)); return y;
}

// ---- precompute cos/sin(phase) per (relation, dim): only 2560 values ----
__global__ void trig_kernel(const float* __restrict__ rel) {
    int i = blockIdx.x * blockDim.x + threadIdx.x;
    if (i < RR * DD) {
        float ph = rel[i] * PHASE_SCALE;
        float s, c;
        sincosf(ph, &s, &c);
        g_cr[i] = c;
        g_sr[i] = s;
    }
}

// ---- CSR build: histogram -> single-block scan -> permuted fill ----
__global__ void hist_kernel(const int* __restrict__ edst) {
    int e = blockIdx.x * blockDim.x + threadIdx.x;
    if (e < EE) atomicAdd(&g_cnt[edst[e]], 1);
}

__global__ void scan_kernel() {
    constexpr int CHUNK = (NN + 1023) / 1024;  // 98
    __shared__ int ssum[1024];
    int t = threadIdx.x;
    int base = t * CHUNK;
    int s = 0;
#pragma unroll 4
    for (int i = 0; i < CHUNK; i++) {
        int idx = base + i;
        if (idx < NN) s += g_cnt[idx];
    }
    ssum[t] = s;
    __syncthreads();
    for (int off = 1; off < 1024; off <<= 1) {
        int u = (t >= off) ? ssum[t - off] : 0;
        __syncthreads();
        ssum[t] += u;
        __syncthreads();
    }
    int run = ssum[t] - s;  // exclusive prefix of this thread's chunk
    for (int i = 0; i < CHUNK; i++) {
        int idx = base + i;
        if (idx < NN) {
            g_rowptr[idx] = run;
            g_cursor[idx] = run;
            run += g_cnt[idx];
        }
    }
    if (t == 0) g_rowptr[NN] = EE;
}

__global__ void fill_kernel(const int* __restrict__ esrc,
                            const int* __restrict__ edst,
                            const int* __restrict__ etyp) {
    int e = blockIdx.x * blockDim.x + threadIdx.x;
    if (e < EE) {
        int d = edst[e];
        int pos = atomicAdd(&g_cursor[d], 1);
        g_src_p[pos] = esrc[e];
        g_dst_p[pos] = d;
        g_typ_p[pos] = etyp[e];
    }
}

__device__ __forceinline__ float edge_term(float rh, float ih, float rt, float it,
                                           float c, float s) {
    float rs = rh * c - ih * s - rt;
    float is = rh * s + ih * c - it;
    return fsqrt_approx(rs * rs + is * is);
}

// ---- raw attention score per (permuted) edge: one warp per edge ----
// Row layout [re(0..63), im(0..63)]; lane l loads float4 at 4l. Lanes 0..15
// hold re-dims, 16..31 the matching im-dims; shfl_xor(16) pairs them.
// Permuted order groups edges by dst -> the t-row hits L1/L2 repeatedly.
__global__ void att_kernel(const float* __restrict__ ent) {
    int e = (blockIdx.x * blockDim.x + threadIdx.x) >> 5;
    int lane = threadIdx.x & 31;
    if (e >= EE) return;
    int s = g_src_p[e], d = g_dst_p[e], t = g_typ_p[e];
    float4 h4 = *(const float4*)(ent + (size_t)s * 128 + lane * 4);
    float4 t4 = *(const float4*)(ent + (size_t)d * 128 + lane * 4);
    float ihx = __shfl_xor_sync(0xffffffffu, h4.x, 16);
    float ihy = __shfl_xor_sync(0xffffffffu, h4.y, 16);
    float ihz = __shfl_xor_sync(0xffffffffu, h4.z, 16);
    float ihw = __shfl_xor_sync(0xffffffffu, h4.w, 16);
    float itx = __shfl_xor_sync(0xffffffffu, t4.x, 16);
    float ity = __shfl_xor_sync(0xffffffffu, t4.y, 16);
    float itz = __shfl_xor_sync(0xffffffffu, t4.z, 16);
    float itw = __shfl_xor_sync(0xffffffffu, t4.w, 16);

    float term = 0.f;
    if (lane < 16) {
        float4 c4 = *(const float4*)(g_cr + t * DD + lane * 4);
        float4 s4 = *(const float4*)(g_sr + t * DD + lane * 4);
        term  = edge_term(h4.x, ihx, t4.x, itx, c4.x, s4.x);
        term += edge_term(h4.y, ihy, t4.y, ity, c4.y, s4.y);
        term += edge_term(h4.z, ihz, t4.z, itz, c4.z, s4.z);
        term += edge_term(h4.w, ihw, t4.w, itw, c4.w, s4.w);
    }
    term += __shfl_xor_sync(0xffffffffu, term, 8);
    term += __shfl_xor_sync(0xffffffffu, term, 4);
    term += __shfl_xor_sync(0xffffffffu, term, 2);
    term += __shfl_xor_sync(0xffffffffu, term, 1);
    if (lane == 0) g_att[e] = term;
}

// ---- fused per-node softmax over the contiguous CSR slice (no atomics) ----
__global__ void softmax_kernel() {
    int n = blockIdx.x * blockDim.x + threadIdx.x;
    if (n >= NN) return;
    int a = g_rowptr[n], b = g_rowptr[n + 1];
    if (a == b) return;
    float m = -1e30f;
    for (int p = a; p < b; p++) m = fmaxf(m, g_att[p]);
    float s = 0.f;
    for (int p = a; p < b; p++) {
        float v = __expf(g_att[p] - m);
        g_att[p] = v;
        s += v;
    }
    float inv = 1.f / s;
    for (int p = a; p < b; p++) g_att[p] *= inv;
}

// ---- side[n] = sum over incoming edges of att * ego[src] (pure gather) ----
// Thread covers (node, 4-float chunk): CH consecutive threads per node ->
// the gathered ego rows are read coalesced; att/src are warp-broadcast.
template <int DIN>
__global__ void agg_kernel(const float* __restrict__ ego, float* __restrict__ side) {
    constexpr int CH = DIN / 4;
    int tid = blockIdx.x * blockDim.x + threadIdx.x;
    int n = tid / CH;
    int c = tid - n * CH;
    if (n >= NN) return;
    int a = g_rowptr[n], b = g_rowptr[n + 1];
    float4 acc = {0.f, 0.f, 0.f, 0.f};
    for (int p = a; p < b; p++) {
        float w = g_att[p];
        int s = g_src_p[p];
        float4 v = *(const float4*)(ego + (size_t)s * DIN + c * 4);
        acc.x += w * v.x; acc.y += w * v.y; acc.z += w * v.z; acc.w += w * v.w;
    }
    *(float4*)(side + (size_t)n * DIN + c * 4) = acc;
}

// ---- per-node dense layer (unchanged from R1) ----
template <int DIN, int DOUT, int Y>
__global__ void layer_kernel(const float* __restrict__ ego,
                             const float* __restrict__ W1, const float* __restrict__ b1,
                             const float* __restrict__ W2, const float* __restrict__ b2,
                             float* __restrict__ ego_out,
                             float* __restrict__ out, int out_col) {
    constexpr int XT = DOUT / 8;
    extern __shared__ float sh[];
    float* w1s = sh;                       // DIN*DOUT
    float* w2s = w1s + DIN * DOUT;         // DIN*DOUT
    float* sa  = w2s + DIN * DOUT;         // Y*(DIN+1)
    float* smm = sa + Y * (DIN + 1);       // Y*(DIN+1)
    float* nrm = smm + Y * (DIN + 1);      // Y

    int tid = threadIdx.y * XT + threadIdx.x;
    constexpr int NT = XT * Y;

    for (int i = tid; i < DIN * DOUT; i += NT) { w1s[i] = W1[i]; w2s[i] = W2[i]; }

    int nbase = blockIdx.x * Y;
    for (int i = tid; i < Y * DIN; i += NT) {
        int yl = i / DIN, k = i - yl * DIN;
        int n = nbase + yl;
        float ev = 0.f, sv = 0.f;
        if (n < NN) {
            ev = ego[(size_t)n * DIN + k];
            sv = g_side[(size_t)n * DIN + k];
        }
        sa[yl * (DIN + 1) + k]  = ev + sv;
        smm[yl * (DIN + 1) + k] = ev * sv;
    }
    for (int i = tid; i < Y; i += NT) nrm[i] = 0.f;
    __syncthreads();

    int x = threadIdx.x, y = threadIdx.y;
    float acc1[8], acc2[8];
#pragma unroll
    for (int j = 0; j < 8; j++) { acc1[j] = b1[x * 8 + j]; acc2[j] = b2[x * 8 + j]; }

    const float* ap = sa + y * (DIN + 1);
    const float* mp = smm + y * (DIN + 1);
#pragma unroll 4
    for (int k = 0; k < DIN; k++) {
        float a = ap[k], m = mp[k];
        const float4* w1p = (const float4*)(w1s + k * DOUT + x * 8);
        const float4* w2p = (const float4*)(w2s + k * DOUT + x * 8);
        float4 wa = w1p[0], wb = w1p[1];
        float4 wc = w2p[0], wd = w2p[1];
        acc1[0] += a * wa.x; acc1[1] += a * wa.y; acc1[2] += a * wa.z; acc1[3] += a * wa.w;
        acc1[4] += a * wb.x; acc1[5] += a * wb.y; acc1[6] += a * wb.z; acc1[7] += a * wb.w;
        acc2[0] += m * wc.x; acc2[1] += m * wc.y; acc2[2] += m * wc.z; acc2[3] += m * wc.w;
        acc2[4] += m * wd.x; acc2[5] += m * wd.y; acc2[6] += m * wd.z; acc2[7] += m * wd.w;
    }

    float vloc[8];
    float ss = 0.f;
#pragma unroll
    for (int j = 0; j < 8; j++) {
        float o1 = acc1[j] > 0.f ? acc1[j] : 0.01f * acc1[j];
        float o2 = acc2[j] > 0.f ? acc2[j] : 0.01f * acc2[j];
        float v = o1 + o2;
        vloc[j] = v;
        ss += v * v;
    }
    atomicAdd(&nrm[y], ss);
    __syncthreads();

    int n = nbase + y;
    if (n < NN) {
        float inv = 1.f / fmaxf(sqrtf(nrm[y]), 1e-12f);
#pragma unroll
        for (int j = 0; j < 8; j++) {
            int col = x * 8 + j;
            ego_out[(size_t)n * DOUT + col] = vloc[j];
            out[(size_t)n * 240 + out_col + col] = vloc[j] * inv;
        }
    }
}

// ---- copy raw ent_embed into output columns [0,128) ----
__global__ void copy_kernel(const float* __restrict__ ent, float* __restrict__ out) {
    int i = blockIdx.x * blockDim.x + threadIdx.x;
    if (i < NN * 128) {
        int n = i >> 7, k = i & 127;
        out[(size_t)n * 240 + k] = ent[i];
    }
}

extern "C" void kernel_launch(void* const* d_in, const int* in_sizes, int n_in,
                              void* d_out, int out_size) {
    const float* ent  = (const float*)d_in[0];
    const float* rel  = (const float*)d_in[1];
    const float* W1_0 = (const float*)d_in[2];
    const float* b1_0 = (const float*)d_in[3];
    const float* W2_0 = (const float*)d_in[4];
    const float* b2_0 = (const float*)d_in[5];
    const float* W1_1 = (const float*)d_in[6];
    const float* b1_1 = (const float*)d_in[7];
    const float* W2_1 = (const float*)d_in[8];
    const float* b2_1 = (const float*)d_in[9];
    const float* W1_2 = (const float*)d_in[10];
    const float* b1_2 = (const float*)d_in[11];
    const float* W2_2 = (const float*)d_in[12];
    const float* b2_2 = (const float*)d_in[13];
    const int* esrc = (const int*)d_in[14];
    const int* edst = (const int*)d_in[15];
    const int* etyp = (const int*)d_in[16];
    float* out = (float*)d_out;

    void *p_cnt, *p_side, *p_ego1, *p_ego2, *p_ego3;
    cudaGetSymbolAddress(&p_cnt, g_cnt);
    cudaGetSymbolAddress(&p_side, g_side);
    cudaGetSymbolAddress(&p_ego1, g_ego1);
    cudaGetSymbolAddress(&p_ego2, g_ego2);
    cudaGetSymbolAddress(&p_ego3, g_ego3);

    cudaFuncSetAttribute(layer_kernel<128, 64, 32>,
                         cudaFuncAttributeMaxDynamicSharedMemorySize, 98688);
    cudaFuncSetAttribute(layer_kernel<64, 32, 64>,
                         cudaFuncAttributeMaxDynamicSharedMemorySize, 49920);
    cudaFuncSetAttribute(layer_kernel<32, 16, 128>,
                         cudaFuncAttributeMaxDynamicSharedMemorySize, 38400);

    // CSR build (reused by softmax + all 3 aggregations)
    cudaMemsetAsync(p_cnt, 0, NN * sizeof(int));
    trig_kernel<<<(RR * DD + 255) / 256, 256>>>(rel);
    hist_kernel<<<(EE + 255) / 256, 256>>>(edst);
    scan_kernel<<<1, 1024>>>();
    fill_kernel<<<(EE + 255) / 256, 256>>>(esrc, edst, etyp);

    att_kernel<<<EE / 8, 256>>>(ent);                 // warp per edge
    softmax_kernel<<<(NN + 255) / 256, 256>>>();
    copy_kernel<<<(NN * 128 + 255) / 256, 256>>>(ent, out);

    // layer 0 (din=128 -> dout=64)
    agg_kernel<128><<<(NN * 32 + 255) / 256, 256>>>(ent, (float*)p_side);
    layer_kernel<128, 64, 32><<<(NN + 31) / 32, dim3(8, 32), 98688>>>(
        ent, W1_0, b1_0, W2_0, b2_0, (float*)p_ego1, out, 128);

    // layer 1 (64 -> 32)
    agg_kernel<64><<<(NN * 16 + 255) / 256, 256>>>((const float*)p_ego1, (float*)p_side);
    layer_kernel<64, 32, 64><<<(NN + 63) / 64, dim3(4, 64), 49920>>>(
        (const float*)p_ego1, W1_1, b1_1, W2_1, b2_1, (float*)p_ego2, out, 192);

    // layer 2 (32 -> 16)
    agg_kernel<32><<<(NN * 8 + 255) / 256, 256>>>((const float*)p_ego2, (float*)p_side);
    layer_kernel<32, 16, 128><<<(NN + 127) / 128, dim3(2, 128), 38400>>>(
        (const float*)p_ego2, W1_2, b1_2, W2_2, b2_2, (float*)p_ego3, out, 224);
}

// round 3
// speedup vs baseline: 1.5439x; 1.5439x over previous
#include <cuda_runtime.h>
#include <math.h>

#define NN 100000
#define EE 1000000
#define RR 40
#define DD 64

static constexpr float PHASE_SCALE = (float)(3.1415926235897933 / ((12.0 + 2.0) / 64.0));

// ---- scratch (device globals: no runtime allocation allowed) ----
__device__ float g_att[EE];
__device__ float g_segmax[NN];
__device__ float g_segsum[NN];
__device__ float g_side[(size_t)NN * 128];
__device__ float g_ego1[(size_t)NN * 64];
__device__ float g_ego2[(size_t)NN * 32];
__device__ float g_ego3[(size_t)NN * 16];
__device__ float g_cr[RR * DD];
__device__ float g_sr[RR * DD];

__device__ __forceinline__ float fsqrt_approx(float x) {
    float y; asm("sqrt.approx.f32 %0, %1;" : "=f"(y) : "f"(x)); return y;
}

// ---- precompute cos/sin(phase) per (relation, dim): only 2560 values ----
__global__ void trig_kernel(const float* __restrict__ rel) {
    int i = blockIdx.x * blockDim.x + threadIdx.x;
    if (i < RR * DD) {
        float ph = rel[i] * PHASE_SCALE;
        float s, c;
        sincosf(ph, &s, &c);
        g_cr[i] = c;
        g_sr[i] = s;
    }
}

__device__ __forceinline__ float edge_term(float rh, float ih, float rt, float it,
                                           float c, float s) {
    float rs = rh * c - ih * s - rt;
    float is = rh * s + ih * c - it;
    return fsqrt_approx(rs * rs + is * is);
}

// ---- raw attention score per edge: one warp per edge ----
__global__ void att_kernel(const float* __restrict__ ent,
                           const int* __restrict__ esrc,
                           const int* __restrict__ edst,
                           const int* __restrict__ etyp) {
    int e = (blockIdx.x * blockDim.x + threadIdx.x) >> 5;
    int lane = threadIdx.x & 31;
    if (e >= EE) return;
    int s = esrc[e], d = edst[e], t = etyp[e];
    float4 h4 = *(const float4*)(ent + (size_t)s * 128 + lane * 4);
    float4 t4 = *(const float4*)(ent + (size_t)d * 128 + lane * 4);
    float ihx = __shfl_xor_sync(0xffffffffu, h4.x, 16);
    float ihy = __shfl_xor_sync(0xffffffffu, h4.y, 16);
    float ihz = __shfl_xor_sync(0xffffffffu, h4.z, 16);
    float ihw = __shfl_xor_sync(0xffffffffu, h4.w, 16);
    float itx = __shfl_xor_sync(0xffffffffu, t4.x, 16);
    float ity = __shfl_xor_sync(0xffffffffu, t4.y, 16);
    float itz = __shfl_xor_sync(0xffffffffu, t4.z, 16);
    float itw = __shfl_xor_sync(0xffffffffu, t4.w, 16);

    float term = 0.f;
    if (lane < 16) {
        float4 c4 = *(const float4*)(g_cr + t * DD + lane * 4);
        float4 s4 = *(const float4*)(g_sr + t * DD + lane * 4);
        term  = edge_term(h4.x, ihx, t4.x, itx, c4.x, s4.x);
        term += edge_term(h4.y, ihy, t4.y, ity, c4.y, s4.y);
        term += edge_term(h4.z, ihz, t4.z, itz, c4.z, s4.z);
        term += edge_term(h4.w, ihw, t4.w, itw, c4.w, s4.w);
    }
    term += __shfl_xor_sync(0xffffffffu, term, 8);
    term += __shfl_xor_sync(0xffffffffu, term, 4);
    term += __shfl_xor_sync(0xffffffffu, term, 2);
    term += __shfl_xor_sync(0xffffffffu, term, 1);
    if (lane == 0) g_att[e] = term;
}

// ---- edge softmax: max, exp+sum (normalization folded into scatter) ----
// scores are >= 0, so int-compare atomicMax on float bits is exact; init=0 ok.
__global__ void segmax_kernel(const int* __restrict__ edst) {
    int e = blockIdx.x * blockDim.x + threadIdx.x;
    if (e < EE)
        atomicMax((int*)&g_segmax[edst[e]], __float_as_int(g_att[e]));
}

__global__ void expsum_kernel(const int* __restrict__ edst) {
    int e = blockIdx.x * blockDim.x + threadIdx.x;
    if (e < EE) {
        int d = edst[e];
        float v = __expf(g_att[e] - g_segmax[d]);
        g_att[e] = v;
        atomicAdd(&g_segsum[d], v);
    }
}

// ---- side[dst] += (att/segsum[dst]) * ego[src]; vector red.v4 reductions ----
// CH consecutive threads cover one edge's row; each does ONE red.global.add.v4
// instead of 4 scalar atomicAdds (4x fewer REDG ops at the LSU/LTS).
template <int DIN>
__global__ void scatter_kernel(const float* __restrict__ ego,
                               const int* __restrict__ esrc,
                               const int* __restrict__ edst) {
    constexpr int CH = DIN / 4;
    int idx = blockIdx.x * blockDim.x + threadIdx.x;
    int e = idx / CH;
    int c = idx - e * CH;
    if (e >= EE) return;
    int d = edst[e];
    float a = __fdividef(g_att[e], g_segsum[d]);
    int s = esrc[e];
    float4 v = *(const float4*)(ego + (size_t)s * DIN + c * 4);
    float* o = g_side + (size_t)d * DIN + c * 4;
    asm volatile("red.global.add.v4.f32 [%0], {%1, %2, %3, %4};"
                 :: "l"(o), "f"(a * v.x), "f"(a * v.y), "f"(a * v.z), "f"(a * v.w)
                 : "memory");
}

// ---- per-node dense layer (as R1) ----
template <int DIN, int DOUT, int Y>
__global__ void layer_kernel(const float* __restrict__ ego,
                             const float* __restrict__ W1, const float* __restrict__ b1,
                             const float* __restrict__ W2, const float* __restrict__ b2,
                             float* __restrict__ ego_out,
                             float* __restrict__ out, int out_col) {
    constexpr int XT = DOUT / 8;
    extern __shared__ float sh[];
    float* w1s = sh;                       // DIN*DOUT
    float* w2s = w1s + DIN * DOUT;         // DIN*DOUT
    float* sa  = w2s + DIN * DOUT;         // Y*(DIN+1)
    float* smm = sa + Y * (DIN + 1);       // Y*(DIN+1)
    float* nrm = smm + Y * (DIN + 1);      // Y

    int tid = threadIdx.y * XT + threadIdx.x;
    constexpr int NT = XT * Y;

    for (int i = tid; i < DIN * DOUT; i += NT) { w1s[i] = W1[i]; w2s[i] = W2[i]; }

    int nbase = blockIdx.x * Y;
    for (int i = tid; i < Y * DIN; i += NT) {
        int yl = i / DIN, k = i - yl * DIN;
        int n = nbase + yl;
        float ev = 0.f, sv = 0.f;
        if (n < NN) {
            ev = ego[(size_t)n * DIN + k];
            sv = g_side[(size_t)n * DIN + k];
        }
        sa[yl * (DIN + 1) + k]  = ev + sv;
        smm[yl * (DIN + 1) + k] = ev * sv;
    }
    for (int i = tid; i < Y; i += NT) nrm[i] = 0.f;
    __syncthreads();

    int x = threadIdx.x, y = threadIdx.y;
    float acc1[8], acc2[8];
#pragma unroll
    for (int j = 0; j < 8; j++) { acc1[j] = b1[x * 8 + j]; acc2[j] = b2[x * 8 + j]; }

    const float* ap = sa + y * (DIN + 1);
    const float* mp = smm + y * (DIN + 1);
#pragma unroll 4
    for (int k = 0; k < DIN; k++) {
        float a = ap[k], m = mp[k];
        const float4* w1p = (const float4*)(w1s + k * DOUT + x * 8);
        const float4* w2p = (const float4*)(w2s + k * DOUT + x * 8);
        float4 wa = w1p[0], wb = w1p[1];
        float4 wc = w2p[0], wd = w2p[1];
        acc1[0] += a * wa.x; acc1[1] += a * wa.y; acc1[2] += a * wa.z; acc1[3] += a * wa.w;
        acc1[4] += a * wb.x; acc1[5] += a * wb.y; acc1[6] += a * wb.z; acc1[7] += a * wb.w;
        acc2[0] += m * wc.x; acc2[1] += m * wc.y; acc2[2] += m * wc.z; acc2[3] += m * wc.w;
        acc2[4] += m * wd.x; acc2[5] += m * wd.y; acc2[6] += m * wd.z; acc2[7] += m * wd.w;
    }

    float vloc[8];
    float ss = 0.f;
#pragma unroll
    for (int j = 0; j < 8; j++) {
        float o1 = acc1[j] > 0.f ? acc1[j] : 0.01f * acc1[j];
        float o2 = acc2[j] > 0.f ? acc2[j] : 0.01f * acc2[j];
        float v = o1 + o2;
        vloc[j] = v;
        ss += v * v;
    }
    atomicAdd(&nrm[y], ss);
    __syncthreads();

    int n = nbase + y;
    if (n < NN) {
        float inv = 1.f / fmaxf(sqrtf(nrm[y]), 1e-12f);
#pragma unroll
        for (int j = 0; j < 8; j++) {
            int col = x * 8 + j;
            ego_out[(size_t)n * DOUT + col] = vloc[j];
            out[(size_t)n * 240 + out_col + col] = vloc[j] * inv;
        }
    }
}

// ---- copy raw ent_embed into output columns [0,128) ----
__global__ void copy_kernel(const float* __restrict__ ent, float* __restrict__ out) {
    int i = blockIdx.x * blockDim.x + threadIdx.x;
    if (i < NN * 128) {
        int n = i >> 7, k = i & 127;
        out[(size_t)n * 240 + k] = ent[i];
    }
}

extern "C" void kernel_launch(void* const* d_in, const int* in_sizes, int n_in,
                              void* d_out, int out_size) {
    const float* ent  = (const float*)d_in[0];
    const float* rel  = (const float*)d_in[1];
    const float* W1_0 = (const float*)d_in[2];
    const float* b1_0 = (const float*)d_in[3];
    const float* W2_0 = (const float*)d_in[4];
    const float* b2_0 = (const float*)d_in[5];
    const float* W1_1 = (const float*)d_in[6];
    const float* b1_1 = (const float*)d_in[7];
    const float* W2_1 = (const float*)d_in[8];
    const float* b2_1 = (const float*)d_in[9];
    const float* W1_2 = (const float*)d_in[10];
    const float* b1_2 = (const float*)d_in[11];
    const float* W2_2 = (const float*)d_in[12];
    const float* b2_2 = (const float*)d_in[13];
    const int* esrc = (const int*)d_in[14];
    const int* edst = (const int*)d_in[15];
    const int* etyp = (const int*)d_in[16];
    float* out = (float*)d_out;

    void *p_max, *p_sum, *p_side, *p_ego1, *p_ego2, *p_ego3;
    cudaGetSymbolAddress(&p_max, g_segmax);
    cudaGetSymbolAddress(&p_sum, g_segsum);
    cudaGetSymbolAddress(&p_side, g_side);
    cudaGetSymbolAddress(&p_ego1, g_ego1);
    cudaGetSymbolAddress(&p_ego2, g_ego2);
    cudaGetSymbolAddress(&p_ego3, g_ego3);

    cudaFuncSetAttribute(layer_kernel<128, 64, 32>,
                         cudaFuncAttributeMaxDynamicSharedMemorySize, 98688);
    cudaFuncSetAttribute(layer_kernel<64, 32, 64>,
                         cudaFuncAttributeMaxDynamicSharedMemorySize, 49920);
    cudaFuncSetAttribute(layer_kernel<32, 16, 128>,
                         cudaFuncAttributeMaxDynamicSharedMemorySize, 38400);

    cudaMemsetAsync(p_max, 0, NN * sizeof(float));
    cudaMemsetAsync(p_sum, 0, NN * sizeof(float));

    // launch order chosen so the profiler's capture slot (~5th-6th launch)
    // lands on att_kernel — the biggest unmeasured kernel.
    trig_kernel<<<(RR * DD + 255) / 256, 256>>>(rel);
    copy_kernel<<<(NN * 128 + 255) / 256, 256>>>(ent, out);
    att_kernel<<<EE / 8, 256>>>(ent, esrc, edst, etyp);            // warp/edge
    segmax_kernel<<<(EE + 255) / 256, 256>>>(edst);
    expsum_kernel<<<(EE + 255) / 256, 256>>>(edst);

    // layer 0 (din=128 -> dout=64)
    cudaMemsetAsync(p_side, 0, (size_t)NN * 128 * sizeof(float));
    scatter_kernel<128><<<EE * 32 / 256, 256>>>(ent, esrc, edst);
    layer_kernel<128, 64, 32><<<(NN + 31) / 32, dim3(8, 32), 98688>>>(
        ent, W1_0, b1_0, W2_0, b2_0, (float*)p_ego1, out, 128);

    // layer 1 (64 -> 32)
    cudaMemsetAsync(p_side, 0, (size_t)NN * 64 * sizeof(float));
    scatter_kernel<64><<<EE * 16 / 256, 256>>>((const float*)p_ego1, esrc, edst);
    layer_kernel<64, 32, 64><<<(NN + 63) / 64, dim3(4, 64), 49920>>>(
        (const float*)p_ego1, W1_1, b1_1, W2_1, b2_1, (float*)p_ego2, out, 192);

    // layer 2 (32 -> 16)
    cudaMemsetAsync(p_side, 0, (size_t)NN * 32 * sizeof(float));
    scatter_kernel<32><<<EE * 8 / 256, 256>>>((const float*)p_ego2, esrc, edst);
    layer_kernel<32, 16, 128><<<(NN + 127) / 128, dim3(2, 128), 38400>>>(
        (const float*)p_ego2, W1_2, b1_2, W2_2, b2_2, (float*)p_ego3, out, 224);
}

// round 4
// speedup vs baseline: 1.5633x; 1.0126x over previous
#include <cuda_runtime.h>
#include <math.h>

#define NN 100000
#define EE 1000000
#define RR 40
#define DD 64

static constexpr float PHASE_SCALE = (float)(3.1415926235897933 / ((12.0 + 2.0) / 64.0));

// ---- scratch (device globals: no runtime allocation allowed) ----
__device__ int   g_cnt[NN];
__device__ int   g_cursor[NN];
__device__ int   g_src_p[EE];
__device__ int   g_dst_p[EE];
__device__ int   g_typ_p[EE];
__device__ float g_att[EE];
__device__ float g_segmax[NN];
__device__ float g_segsum[NN];
__device__ float g_side[(size_t)NN * 128];
__device__ float g_ego1[(size_t)NN * 64];
__device__ float g_ego2[(size_t)NN * 32];
__device__ float g_ego3[(size_t)NN * 16];
__device__ float g_cr[RR * DD];
__device__ float g_sr[RR * DD];

__device__ __forceinline__ float fsqrt_approx(float x) {
    float y; asm("sqrt.approx.f32 %0, %1;" : "=f"(y) : "f"(x)); return y;
}

// ---- CSR-permutation build: histogram -> single-block scan -> fill ----
__global__ void hist_kernel(const int* __restrict__ edst) {
    int e = blockIdx.x * blockDim.x + threadIdx.x;
    if (e < EE) atomicAdd(&g_cnt[edst[e]], 1);
}

__global__ void scan_kernel() {
    constexpr int CHUNK = (NN + 1023) / 1024;  // 98
    __shared__ int ssum[1024];
    int t = threadIdx.x;
    int base = t * CHUNK;
    int s = 0;
#pragma unroll 4
    for (int i = 0; i < CHUNK; i++) {
        int idx = base + i;
        if (idx < NN) s += g_cnt[idx];
    }
    ssum[t] = s;
    __syncthreads();
    for (int off = 1; off < 1024; off <<= 1) {
        int u = (t >= off) ? ssum[t - off] : 0;
        __syncthreads();
        ssum[t] += u;
        __syncthreads();
    }
    int run = ssum[t] - s;  // exclusive prefix of this chunk
    for (int i = 0; i < CHUNK; i++) {
        int idx = base + i;
        if (idx < NN) {
            g_cursor[idx] = run;
            run += g_cnt[idx];
        }
    }
}

__global__ void fill_kernel(const int* __restrict__ esrc,
                            const int* __restrict__ edst,
                            const int* __restrict__ etyp) {
    int e = blockIdx.x * blockDim.x + threadIdx.x;
    if (e < EE) {
        int d = edst[e];
        int pos = atomicAdd(&g_cursor[d], 1);
        g_src_p[pos] = esrc[e];
        g_dst_p[pos] = d;
        g_typ_p[pos] = etyp[e];
    }
}

// ---- precompute cos/sin(phase) per (relation, dim): only 2560 values ----
__global__ void trig_kernel(const float* __restrict__ rel) {
    int i = blockIdx.x * blockDim.x + threadIdx.x;
    if (i < RR * DD) {
        float ph = rel[i] * PHASE_SCALE;
        float s, c;
        sincosf(ph, &s, &c);
        g_cr[i] = c;
        g_sr[i] = s;
    }
}

__device__ __forceinline__ float edge_term(float rh, float ih, float rt, float it,
                                           float c, float s) {
    float rs = rh * c - ih * s - rt;
    float is = rh * s + ih * c - it;
    return fsqrt_approx(rs * rs + is * is);
}

// ---- raw attention score per (permuted) edge: one warp per edge ----
// Row layout [re(0..63), im(0..63)]; lane l loads float4 at 4l. Lanes 0..15
// hold re-dims, 16..31 the matching im-dims; shfl_xor(16) pairs them.
// Sorted order groups edges by dst -> the dst row hits L1/L2 repeatedly.
__global__ void att_kernel(const float* __restrict__ ent) {
    int e = (blockIdx.x * blockDim.x + threadIdx.x) >> 5;
    int lane = threadIdx.x & 31;
    if (e >= EE) return;
    int s = g_src_p[e], d = g_dst_p[e], t = g_typ_p[e];
    float4 h4 = *(const float4*)(ent + (size_t)s * 128 + lane * 4);
    float4 t4 = *(const float4*)(ent + (size_t)d * 128 + lane * 4);
    float ihx = __shfl_xor_sync(0xffffffffu, h4.x, 16);
    float ihy = __shfl_xor_sync(0xffffffffu, h4.y, 16);
    float ihz = __shfl_xor_sync(0xffffffffu, h4.z, 16);
    float ihw = __shfl_xor_sync(0xffffffffu, h4.w, 16);
    float itx = __shfl_xor_sync(0xffffffffu, t4.x, 16);
    float ity = __shfl_xor_sync(0xffffffffu, t4.y, 16);
    float itz = __shfl_xor_sync(0xffffffffu, t4.z, 16);
    float itw = __shfl_xor_sync(0xffffffffu, t4.w, 16);

    float term = 0.f;
    if (lane < 16) {
        float4 c4 = *(const float4*)(g_cr + t * DD + lane * 4);
        float4 s4 = *(const float4*)(g_sr + t * DD + lane * 4);
        term  = edge_term(h4.x, ihx, t4.x, itx, c4.x, s4.x);
        term += edge_term(h4.y, ihy, t4.y, ity, c4.y, s4.y);
        term += edge_term(h4.z, ihz, t4.z, itz, c4.z, s4.z);
        term += edge_term(h4.w, ihw, t4.w, itw, c4.w, s4.w);
    }
    term += __shfl_xor_sync(0xffffffffu, term, 8);
    term += __shfl_xor_sync(0xffffffffu, term, 4);
    term += __shfl_xor_sync(0xffffffffu, term, 2);
    term += __shfl_xor_sync(0xffffffffu, term, 1);
    if (lane == 0) g_att[e] = term;
}

// ---- edge softmax (max, exp+sum); normalization folded into scatter ----
// scores >= 0 -> int-compare atomicMax on float bits is exact; init=0 ok.
__global__ void segmax_kernel() {
    int e = blockIdx.x * blockDim.x + threadIdx.x;
    if (e < EE)
        atomicMax((int*)&g_segmax[g_dst_p[e]], __float_as_int(g_att[e]));
}

__global__ void expsum_kernel() {
    int e = blockIdx.x * blockDim.x + threadIdx.x;
    if (e < EE) {
        int d = g_dst_p[e];
        float v = __expf(g_att[e] - g_segmax[d]);
        g_att[e] = v;
        atomicAdd(&g_segsum[d], v);
    }
}

// ---- run-aggregated scatter over dst-sorted edges ----
// Thread = (chunk c, window of 8 consecutive sorted edges). Accumulates
// a*ego[src] in a register while dst is unchanged; flushes ONE
// red.global.add.v4 per run. Avg degree 10 -> ~1.5 flushes per window
// vs 8 before: ~5x fewer fp32 adds at the LTS atomic ALU.
template <int DIN>
__global__ void scatter_agg_kernel(const float* __restrict__ ego) {
    constexpr int CH = DIN / 4;
    int t = blockIdx.x * blockDim.x + threadIdx.x;
    int c = t % CH;           // lanes contiguous in c -> coalesced gather
    int g = t / CH;
    int ebase = g * 8;        // EE divisible by 8
    if (ebase >= EE) return;

    int cur = g_dst_p[ebase];
    float4 acc = {0.f, 0.f, 0.f, 0.f};
#pragma unroll
    for (int i = 0; i < 8; i++) {
        int e = ebase + i;
        int d = g_dst_p[e];
        if (d != cur) {
            float* o = g_side + (size_t)cur * DIN + c * 4;
            asm volatile("red.global.add.v4.f32 [%0], {%1, %2, %3, %4};"
                         :: "l"(o), "f"(acc.x), "f"(acc.y), "f"(acc.z), "f"(acc.w)
                         : "memory");
            acc.x = acc.y = acc.z = acc.w = 0.f;
            cur = d;
        }
        float a = __fdividef(g_att[e], g_segsum[d]);
        int s = g_src_p[e];
        float4 v = *(const float4*)(ego + (size_t)s * DIN + c * 4);
        acc.x += a * v.x; acc.y += a * v.y; acc.z += a * v.z; acc.w += a * v.w;
    }
    float* o = g_side + (size_t)cur * DIN + c * 4;
    asm volatile("red.global.add.v4.f32 [%0], {%1, %2, %3, %4};"
                 :: "l"(o), "f"(acc.x), "f"(acc.y), "f"(acc.z), "f"(acc.w)
                 : "memory");
}

// ---- per-node dense layer (as R1/R3) ----
template <int DIN, int DOUT, int Y>
__global__ void layer_kernel(const float* __restrict__ ego,
                             const float* __restrict__ W1, const float* __restrict__ b1,
                             const float* __restrict__ W2, const float* __restrict__ b2,
                             float* __restrict__ ego_out,
                             float* __restrict__ out, int out_col) {
    constexpr int XT = DOUT / 8;
    extern __shared__ float sh[];
    float* w1s = sh;                       // DIN*DOUT
    float* w2s = w1s + DIN * DOUT;         // DIN*DOUT
    float* sa  = w2s + DIN * DOUT;         // Y*(DIN+1)
    float* smm = sa + Y * (DIN + 1);       // Y*(DIN+1)
    float* nrm = smm + Y * (DIN + 1);      // Y

    int tid = threadIdx.y * XT + threadIdx.x;
    constexpr int NT = XT * Y;

    for (int i = tid; i < DIN * DOUT; i += NT) { w1s[i] = W1[i]; w2s[i] = W2[i]; }

    int nbase = blockIdx.x * Y;
    for (int i = tid; i < Y * DIN; i += NT) {
        int yl = i / DIN, k = i - yl * DIN;
        int n = nbase + yl;
        float ev = 0.f, sv = 0.f;
        if (n < NN) {
            ev = ego[(size_t)n * DIN + k];
            sv = g_side[(size_t)n * DIN + k];
        }
        sa[yl * (DIN + 1) + k]  = ev + sv;
        smm[yl * (DIN + 1) + k] = ev * sv;
    }
    for (int i = tid; i < Y; i += NT) nrm[i] = 0.f;
    __syncthreads();

    int x = threadIdx.x, y = threadIdx.y;
    float acc1[8], acc2[8];
#pragma unroll
    for (int j = 0; j < 8; j++) { acc1[j] = b1[x * 8 + j]; acc2[j] = b2[x * 8 + j]; }

    const float* ap = sa + y * (DIN + 1);
    const float* mp = smm + y * (DIN + 1);
#pragma unroll 4
    for (int k = 0; k < DIN; k++) {
        float a = ap[k], m = mp[k];
        const float4* w1p = (const float4*)(w1s + k * DOUT + x * 8);
        const float4* w2p = (const float4*)(w2s + k * DOUT + x * 8);
        float4 wa = w1p[0], wb = w1p[1];
        float4 wc = w2p[0], wd = w2p[1];
        acc1[0] += a * wa.x; acc1[1] += a * wa.y; acc1[2] += a * wa.z; acc1[3] += a * wa.w;
        acc1[4] += a * wb.x; acc1[5] += a * wb.y; acc1[6] += a * wb.z; acc1[7] += a * wb.w;
        acc2[0] += m * wc.x; acc2[1] += m * wc.y; acc2[2] += m * wc.z; acc2[3] += m * wc.w;
        acc2[4] += m * wd.x; acc2[5] += m * wd.y; acc2[6] += m * wd.z; acc2[7] += m * wd.w;
    }

    float vloc[8];
    float ss = 0.f;
#pragma unroll
    for (int j = 0; j < 8; j++) {
        float o1 = acc1[j] > 0.f ? acc1[j] : 0.01f * acc1[j];
        float o2 = acc2[j] > 0.f ? acc2[j] : 0.01f * acc2[j];
        float v = o1 + o2;
        vloc[j] = v;
        ss += v * v;
    }
    atomicAdd(&nrm[y], ss);
    __syncthreads();

    int n = nbase + y;
    if (n < NN) {
        float inv = 1.f / fmaxf(sqrtf(nrm[y]), 1e-12f);
#pragma unroll
        for (int j = 0; j < 8; j++) {
            int col = x * 8 + j;
            ego_out[(size_t)n * DOUT + col] = vloc[j];
            out[(size_t)n * 240 + out_col + col] = vloc[j] * inv;
        }
    }
}

// ---- copy raw ent_embed into output columns [0,128) ----
__global__ void copy_kernel(const float* __restrict__ ent, float* __restrict__ out) {
    int i = blockIdx.x * blockDim.x + threadIdx.x;
    if (i < NN * 128) {
        int n = i >> 7, k = i & 127;
        out[(size_t)n * 240 + k] = ent[i];
    }
}

extern "C" void kernel_launch(void* const* d_in, const int* in_sizes, int n_in,
                              void* d_out, int out_size) {
    const float* ent  = (const float*)d_in[0];
    const float* rel  = (const float*)d_in[1];
    const float* W1_0 = (const float*)d_in[2];
    const float* b1_0 = (const float*)d_in[3];
    const float* W2_0 = (const float*)d_in[4];
    const float* b2_0 = (const float*)d_in[5];
    const float* W1_1 = (const float*)d_in[6];
    const float* b1_1 = (const float*)d_in[7];
    const float* W2_1 = (const float*)d_in[8];
    const float* b2_1 = (const float*)d_in[9];
    const float* W1_2 = (const float*)d_in[10];
    const float* b1_2 = (const float*)d_in[11];
    const float* W2_2 = (const float*)d_in[12];
    const float* b2_2 = (const float*)d_in[13];
    const int* esrc = (const int*)d_in[14];
    const int* edst = (const int*)d_in[15];
    const int* etyp = (const int*)d_in[16];
    float* out = (float*)d_out;

    void *p_cnt, *p_max, *p_sum, *p_side, *p_ego1, *p_ego2, *p_ego3;
    cudaGetSymbolAddress(&p_cnt, g_cnt);
    cudaGetSymbolAddress(&p_max, g_segmax);
    cudaGetSymbolAddress(&p_sum, g_segsum);
    cudaGetSymbolAddress(&p_side, g_side);
    cudaGetSymbolAddress(&p_ego1, g_ego1);
    cudaGetSymbolAddress(&p_ego2, g_ego2);
    cudaGetSymbolAddress(&p_ego3, g_ego3);

    cudaFuncSetAttribute(layer_kernel<128, 64, 32>,
                         cudaFuncAttributeMaxDynamicSharedMemorySize, 98688);
    cudaFuncSetAttribute(layer_kernel<64, 32, 64>,
                         cudaFuncAttributeMaxDynamicSharedMemorySize, 49920);
    cudaFuncSetAttribute(layer_kernel<32, 16, 128>,
                         cudaFuncAttributeMaxDynamicSharedMemorySize, 38400);

    // CSR permutation build.  Launch order puts att_kernel in the ncu
    // capture slot (6th launch including the memset).
    cudaMemsetAsync(p_cnt, 0, NN * sizeof(int));                 // 1
    hist_kernel<<<(EE + 255) / 256, 256>>>(edst);                // 2
    scan_kernel<<<1, 1024>>>();                                  // 3
    fill_kernel<<<(EE + 255) / 256, 256>>>(esrc, edst, etyp);    // 4
    trig_kernel<<<(RR * DD + 255) / 256, 256>>>(rel);            // 5
    att_kernel<<<EE / 8, 256>>>(ent);                            // 6 <- profiled

    cudaMemsetAsync(p_max, 0, NN * sizeof(float));
    cudaMemsetAsync(p_sum, 0, NN * sizeof(float));
    segmax_kernel<<<(EE + 255) / 256, 256>>>();
    expsum_kernel<<<(EE + 255) / 256, 256>>>();
    copy_kernel<<<(NN * 128 + 255) / 256, 256>>>(ent, out);

    // layer 0 (din=128 -> dout=64)
    cudaMemsetAsync(p_side, 0, (size_t)NN * 128 * sizeof(float));
    scatter_agg_kernel<128><<<(EE / 8 * 32 + 255) / 256, 256>>>(ent);
    layer_kernel<128, 64, 32><<<(NN + 31) / 32, dim3(8, 32), 98688>>>(
        ent, W1_0, b1_0, W2_0, b2_0, (float*)p_ego1, out, 128);

    // layer 1 (64 -> 32)
    cudaMemsetAsync(p_side, 0, (size_t)NN * 64 * sizeof(float));
    scatter_agg_kernel<64><<<(EE / 8 * 16 + 255) / 256, 256>>>((const float*)p_ego1);
    layer_kernel<64, 32, 64><<<(NN + 63) / 64, dim3(4, 64), 49920>>>(
        (const float*)p_ego1, W1_1, b1_1, W2_1, b2_1, (float*)p_ego2, out, 192);

    // layer 2 (32 -> 16)
    cudaMemsetAsync(p_side, 0, (size_t)NN * 32 * sizeof(float));
    scatter_agg_kernel<32><<<(EE / 8 * 8 + 255) / 256, 256>>>((const float*)p_ego2);
    layer_kernel<32, 16, 128><<<(NN + 127) / 128, dim3(2, 128), 38400>>>(
        (const float*)p_ego2, W1_2, b1_2, W2_2, b2_2, (float*)p_ego3, out, 224);
}